// round 2
// baseline (speedup 1.0000x reference)
#include <cuda_runtime.h>

#define CC   64
#define HH   128
#define WW   128
#define BB   8
#define HW   (HH*WW)        // 16384
#define CHW  (CC*HW)        // 1048576

// scratch for feature_xf / feature_xr (concat channels 0-63 / 64-127)
__device__ float g_featF[BB*CC*HH*WW];
__device__ float g_featR[BB*CC*HH*WW];

// ---------------- helpers ----------------

__device__ __forceinline__ void load_row(float* dst, const float* src, int tid) {
    // dst: [64][129] padded, src points at (n, c=0, y, x=0); channel stride HW
    for (int idx = tid; idx < 64*128; idx += 256) {
        int c = idx >> 7, xx = idx & 127;
        dst[c*129 + xx] = src[c*HW + xx];
    }
}

__device__ __forceinline__ void load_w(float* Wst, float* bst,
                                       const float* Wg, const float* bg, int tid) {
    for (int idx = tid; idx < 4096; idx += 256)
        Wst[(idx >> 6)*65 + (idx & 63)] = Wg[idx];
    if (tid < 64) bst[tid] = bg[tid];
}

// out[o][x] accum: o = ty*4+i, x = tx+16j ; A row-stride lda (65), B [64][129]
__device__ __forceinline__ void mm64(const float* __restrict__ A, int lda,
                                     const float* __restrict__ Bm,
                                     int ty, int tx, float acc[4][8]) {
    #pragma unroll
    for (int i = 0; i < 4; i++)
        #pragma unroll
        for (int j = 0; j < 8; j++) acc[i][j] = 0.f;
    #pragma unroll 8
    for (int k = 0; k < 64; k++) {
        float a[4], b[8];
        #pragma unroll
        for (int i = 0; i < 4; i++) a[i] = A[(ty*4+i)*lda + k];
        #pragma unroll
        for (int j = 0; j < 8; j++) b[j] = Bm[k*129 + tx + 16*j];
        #pragma unroll
        for (int i = 0; i < 4; i++)
            #pragma unroll
            for (int j = 0; j < 8; j++) acc[i][j] = fmaf(a[i], b[j], acc[i][j]);
    }
}

// score[c][d] = sum_w Am[c][w]*Bm[d][w], c=ty*4+i, d=tx+16j (j<4), K=128
__device__ __forceinline__ void sc128(const float* __restrict__ Am,
                                      const float* __restrict__ Bm,
                                      int ty, int tx, float acc[4][4]) {
    #pragma unroll
    for (int i = 0; i < 4; i++)
        #pragma unroll
        for (int j = 0; j < 4; j++) acc[i][j] = 0.f;
    #pragma unroll 8
    for (int k = 0; k < 128; k++) {
        float a[4], b[4];
        #pragma unroll
        for (int i = 0; i < 4; i++) a[i] = Am[(ty*4+i)*129 + k];
        #pragma unroll
        for (int j = 0; j < 4; j++) b[j] = Bm[(tx+16*j)*129 + k];
        #pragma unroll
        for (int i = 0; i < 4; i++)
            #pragma unroll
            for (int j = 0; j < 4; j++) acc[i][j] = fmaf(a[i], b[j], acc[i][j]);
    }
}

// ---------------- kernel 1: projections + attention per (n, y) row ----------------
// smem: BufA[64][129], BufP[64][129], BufF[64][129], Sc[64][65], Wst[64][65], bst[64]
#define SMEM1_FLOATS (3*64*129 + 2*64*65 + 64)

__global__ void __launch_bounds__(256, 1)
attn_kernel(const float* __restrict__ x,  const float* __restrict__ xf, const float* __restrict__ xr,
            const float* __restrict__ Wx,  const float* __restrict__ bx,
            const float* __restrict__ Wx1, const float* __restrict__ bx1,
            const float* __restrict__ Wx2, const float* __restrict__ bx2,
            const float* __restrict__ Wxf, const float* __restrict__ bxf,
            const float* __restrict__ Wxr, const float* __restrict__ bxr)
{
    extern __shared__ float sm[];
    float* BufA = sm;                  // X -> T1 -> T2
    float* BufP = BufA + 64*129;       // xp
    float* BufF = BufP + 64*129;       // xf->xfp, then xr->xrp
    float* Sc   = BufF + 64*129;       // score
    float* Wst  = Sc   + 64*65;
    float* bst  = Wst  + 64*65;

    const int tid = threadIdx.x;
    const int ty = tid >> 4, tx = tid & 15;
    const int y = blockIdx.x, n = blockIdx.y;
    const int rowoff = n*CHW + y*WW;

    float acc[4][8];

    // ---- xp = Wx @ x + bx ----
    load_row(BufA, x + rowoff, tid);
    load_w(Wst, bst, Wx, bx, tid);
    __syncthreads();
    mm64(Wst, 65, BufA, ty, tx, acc);
    #pragma unroll
    for (int i = 0; i < 4; i++)
        #pragma unroll
        for (int j = 0; j < 8; j++)
            BufP[(ty*4+i)*129 + tx + 16*j] = acc[i][j] + bst[ty*4+i];
    __syncthreads();

    // ---- xfp = Wxf @ xf + bxf (in place in BufF) ----
    load_row(BufF, xf + rowoff, tid);
    load_w(Wst, bst, Wxf, bxf, tid);
    __syncthreads();
    mm64(Wst, 65, BufF, ty, tx, acc);
    __syncthreads();
    #pragma unroll
    for (int i = 0; i < 4; i++)
        #pragma unroll
        for (int j = 0; j < 8; j++)
            BufF[(ty*4+i)*129 + tx + 16*j] = acc[i][j] + bst[ty*4+i];
    __syncthreads();

    // ---- x1 = Wx1 @ xp + bx1 -> BufA ----
    load_w(Wst, bst, Wx1, bx1, tid);
    __syncthreads();
    mm64(Wst, 65, BufP, ty, tx, acc);
    #pragma unroll
    for (int i = 0; i < 4; i++)
        #pragma unroll
        for (int j = 0; j < 8; j++)
            BufA[(ty*4+i)*129 + tx + 16*j] = acc[i][j] + bst[ty*4+i];
    __syncthreads();

    // ---- score1 = x1 . xfp^T ----
    {
        float s[4][4];
        sc128(BufA, BufF, ty, tx, s);
        #pragma unroll
        for (int i = 0; i < 4; i++)
            #pragma unroll
            for (int j = 0; j < 4; j++)
                Sc[(ty*4+i)*65 + tx + 16*j] = s[i][j];
    }
    __syncthreads();

    // ---- feature_xf = score1 @ xp -> global ----
    mm64(Sc, 65, BufP, ty, tx, acc);
    #pragma unroll
    for (int i = 0; i < 4; i++)
        #pragma unroll
        for (int j = 0; j < 8; j++)
            g_featF[rowoff + (ty*4+i)*HW + tx + 16*j] = acc[i][j];
    __syncthreads();

    // ---- xrp = Wxr @ xr + bxr (in place) ----
    load_row(BufF, xr + rowoff, tid);
    load_w(Wst, bst, Wxr, bxr, tid);
    __syncthreads();
    mm64(Wst, 65, BufF, ty, tx, acc);
    __syncthreads();
    #pragma unroll
    for (int i = 0; i < 4; i++)
        #pragma unroll
        for (int j = 0; j < 8; j++)
            BufF[(ty*4+i)*129 + tx + 16*j] = acc[i][j] + bst[ty*4+i];
    __syncthreads();

    // ---- x2 = Wx2 @ xp + bx2 -> BufA ----
    load_w(Wst, bst, Wx2, bx2, tid);
    __syncthreads();
    mm64(Wst, 65, BufP, ty, tx, acc);
    #pragma unroll
    for (int i = 0; i < 4; i++)
        #pragma unroll
        for (int j = 0; j < 8; j++)
            BufA[(ty*4+i)*129 + tx + 16*j] = acc[i][j] + bst[ty*4+i];
    __syncthreads();

    // ---- score2 = x2 . xrp^T ----
    {
        float s[4][4];
        sc128(BufA, BufF, ty, tx, s);
        #pragma unroll
        for (int i = 0; i < 4; i++)
            #pragma unroll
            for (int j = 0; j < 4; j++)
                Sc[(ty*4+i)*65 + tx + 16*j] = s[i][j];
    }
    __syncthreads();

    // ---- feature_xr = score2 @ xp -> global ----
    mm64(Sc, 65, BufP, ty, tx, acc);
    #pragma unroll
    for (int i = 0; i < 4; i++)
        #pragma unroll
        for (int j = 0; j < 8; j++)
            g_featR[rowoff + (ty*4+i)*HW + tx + 16*j] = acc[i][j];
}

// ---------------- kernel 2: 3x3 conv (192->192) + BN + ReLU ----------------
// block = (y, n, ob) ; ob selects 64 output channels
// smem: As[9][32][65] weights for chunk, Bs[32][130] haloed input row
#define SMEM2_FLOATS (9*32*65 + 32*130)

__global__ void __launch_bounds__(256, 2)
conv_kernel(const float* __restrict__ x,     const float* __restrict__ Wmsa,
            const float* __restrict__ bmsa,  const float* __restrict__ gamma,
            const float* __restrict__ beta,  const float* __restrict__ mean,
            const float* __restrict__ var,   float* __restrict__ out)
{
    extern __shared__ float sm[];
    float* As = sm;             // [9][32][65]
    float* Bs = As + 9*32*65;   // [32][130]

    const int tid = threadIdx.x;
    const int ty = tid >> 4, tx = tid & 15;
    const int y = blockIdx.x, n = blockIdx.y, ob = blockIdx.z;

    float acc[4][8];
    #pragma unroll
    for (int i = 0; i < 4; i++)
        #pragma unroll
        for (int j = 0; j < 8; j++) acc[i][j] = 0.f;

    for (int chunk = 0; chunk < 6; ++chunk) {
        __syncthreads();   // prior reads of As/Bs done
        // ---- weights: 64 o * (32 ci * 9 taps) contiguous per o ----
        const float* wbase = Wmsa + (size_t)(ob*64)*1728 + chunk*288;
        for (int idx = tid; idx < 64*288; idx += 256) {
            int o   = idx / 288;
            int rem = idx - o*288;          // = k*9 + t
            int k   = rem / 9;
            int t   = rem - k*9;
            As[(t*32 + k)*65 + o] = wbase[o*1728 + rem];
        }

        // input source for this 32-channel chunk
        const int ci0 = chunk*32;
        const float* srcbase;
        if      (ci0 < 64)  srcbase = g_featF + n*CHW + ci0*HW;
        else if (ci0 < 128) srcbase = g_featR + n*CHW + (ci0-64)*HW;
        else                srcbase = x       + n*CHW + (ci0-128)*HW;

        for (int kh = 0; kh < 3; ++kh) {
            const int iy = y + kh - 1;
            if (iy < 0 || iy >= HH) continue;   // uniform across block
            __syncthreads();                    // prior compute reads of Bs done (also covers As)
            const float* src = srcbase + iy*WW;
            for (int idx = tid; idx < 32*130; idx += 256) {
                int k = idx / 130, col = idx - k*130;
                int gx = col - 1;
                Bs[k*130 + col] = (gx >= 0 && gx < WW) ? src[k*HW + gx] : 0.f;
            }
            __syncthreads();
            #pragma unroll
            for (int kw = 0; kw < 3; ++kw) {
                const float* Ap = As + (size_t)(kh*3 + kw)*32*65 + ty*4;
                #pragma unroll 4
                for (int k = 0; k < 32; k++) {
                    float a[4], b[8];
                    #pragma unroll
                    for (int i = 0; i < 4; i++) a[i] = Ap[k*65 + i];
                    #pragma unroll
                    for (int j = 0; j < 8; j++) b[j] = Bs[k*130 + tx + 16*j + kw];
                    #pragma unroll
                    for (int i = 0; i < 4; i++)
                        #pragma unroll
                        for (int j = 0; j < 8; j++)
                            acc[i][j] = fmaf(a[i], b[j], acc[i][j]);
                }
            }
        }
    }

    // ---- bias + BN(eval) + ReLU ----
    #pragma unroll
    for (int i = 0; i < 4; i++) {
        const int o = ob*64 + ty*4 + i;
        const float s  = gamma[o] * rsqrtf(var[o] + 1e-4f);
        const float t0 = (bmsa[o] - mean[o]) * s + beta[o];
        float* orow = out + ((size_t)(n*192 + o)*HH + y)*WW;
        #pragma unroll
        for (int j = 0; j < 8; j++) {
            float v = fmaf(acc[i][j], s, t0);
            orow[tx + 16*j] = fmaxf(v, 0.f);
        }
    }
}

// ---------------- launch ----------------

extern "C" void kernel_launch(void* const* d_in, const int* in_sizes, int n_in,
                              void* d_out, int out_size)
{
    const float* x    = (const float*)d_in[0];
    const float* xf   = (const float*)d_in[1];
    const float* xr   = (const float*)d_in[2];
    const float* Wx   = (const float*)d_in[3];
    const float* bx   = (const float*)d_in[4];
    const float* Wx1  = (const float*)d_in[5];
    const float* bx1  = (const float*)d_in[6];
    const float* Wx2  = (const float*)d_in[7];
    const float* bx2  = (const float*)d_in[8];
    const float* Wxf  = (const float*)d_in[9];
    const float* bxf  = (const float*)d_in[10];
    const float* Wxr  = (const float*)d_in[11];
    const float* bxr  = (const float*)d_in[12];
    const float* Wmsa = (const float*)d_in[13];
    const float* bmsa = (const float*)d_in[14];
    const float* gam  = (const float*)d_in[15];
    const float* bet  = (const float*)d_in[16];
    const float* mu   = (const float*)d_in[17];
    const float* var  = (const float*)d_in[18];
    float* out = (float*)d_out;

    const int smem1 = SMEM1_FLOATS * 4;   // 132608 B
    const int smem2 = SMEM2_FLOATS * 4;   //  91520 B
    cudaFuncSetAttribute(attn_kernel, cudaFuncAttributeMaxDynamicSharedMemorySize, smem1);
    cudaFuncSetAttribute(conv_kernel, cudaFuncAttributeMaxDynamicSharedMemorySize, smem2);

    dim3 g1(HH, BB);
    attn_kernel<<<g1, 256, smem1>>>(x, xf, xr, Wx, bx, Wx1, bx1, Wx2, bx2,
                                    Wxf, bxf, Wxr, bxr);

    dim3 g2(HH, BB, 3);
    conv_kernel<<<g2, 256, smem2>>>(x, Wmsa, bmsa, gam, bet, mu, var, out);
}

// round 6
// speedup vs baseline: 1.6596x; 1.6596x over previous
#include <cuda_runtime.h>

typedef unsigned long long ull;

#define CC   64
#define HH   128
#define WW   128
#define BB   8
#define HW   (HH*WW)        // 16384
#define CHW  (CC*HW)        // 1048576

// scratch for feature_xf / feature_xr
__device__ float g_featF[BB*CC*HH*WW];
__device__ float g_featR[BB*CC*HH*WW];

// ---------------- f32x2 helpers ----------------

__device__ __forceinline__ ull pk2(float lo, float hi){
    ull r; asm("mov.b64 %0, {%1,%2};" : "=l"(r) : "f"(lo), "f"(hi)); return r;
}
__device__ __forceinline__ void unpk(ull a, float& lo, float& hi){
    asm("mov.b64 {%0,%1}, %2;" : "=f"(lo), "=f"(hi) : "l"(a));
}
__device__ __forceinline__ void fma2(ull& d, ull a, ull b){
    asm("fma.rn.f32x2 %0, %1, %2, %0;" : "+l"(d) : "l"(a), "l"(b));
}
__device__ __forceinline__ ull add2(ull a, ull b){
    ull r; asm("add.rn.f32x2 %0, %1, %2;" : "=l"(r) : "l"(a), "l"(b)); return r;
}
// (a.hi, b.lo)
__device__ __forceinline__ ull mid2(ull a, ull b){
    ull r;
    asm("{ .reg .b32 x,y,z,w;\n\t"
        "mov.b64 {x,y}, %1;\n\t"
        "mov.b64 {z,w}, %2;\n\t"
        "mov.b64 %0, {y,z}; }" : "=l"(r) : "l"(a), "l"(b));
    return r;
}

// ---------------- attn kernel (per (n,y) row) ----------------
// smem: WS ull[64*65] (duplicated weight pairs / score pairs),
//       BufA/BufP/BufF float[64*130], bst[64]
#define BSTRIDE 130
#define WSTRIDE 65
#define SMEM1_BYTES (64*WSTRIDE*8 + 3*64*BSTRIDE*4 + 64*4)

__device__ __forceinline__ void load_row130(float* dst, const float* src, int tid){
    for (int idx = tid; idx < 64*128; idx += 256) {
        int c = idx >> 7, xx = idx & 127;
        dst[c*BSTRIDE + xx] = src[c*HW + xx];
    }
}
// weights duplicated: WS[k*65+o] = {W[o][k], W[o][k]}
__device__ __forceinline__ void load_wdup(ull* WS, float* bst,
                                          const float* Wg, const float* bg, int tid){
    for (int idx = tid; idx < 4096; idx += 256) {
        int o = idx >> 6, k = idx & 63;
        float w = Wg[idx];
        WS[k*WSTRIDE + o] = pk2(w, w);
    }
    if (tid < 64) bst[tid] = bg[tid];
}

// out[o][pixpair]: o=o0+i, pixel pair P=2tx+32jj; A2[k*65+o] = dup pairs
__device__ __forceinline__ void mm64p(const ull* __restrict__ A2,
                                      const float* __restrict__ Bm,
                                      int o0, int tx, ull acc[4][4]){
    #pragma unroll
    for (int i = 0; i < 4; i++)
        #pragma unroll
        for (int j = 0; j < 4; j++) acc[i][j] = 0ull;
    #pragma unroll 4
    for (int k = 0; k < 64; k++) {
        ull a0 = A2[k*WSTRIDE + o0    ];
        ull a1 = A2[k*WSTRIDE + o0 + 1];
        ull a2 = A2[k*WSTRIDE + o0 + 2];
        ull a3 = A2[k*WSTRIDE + o0 + 3];
        const float* bp = Bm + k*BSTRIDE + 2*tx;
        #pragma unroll
        for (int jj = 0; jj < 4; jj++) {
            ull b = *reinterpret_cast<const ull*>(bp + 32*jj);
            fma2(acc[0][jj], a0, b);
            fma2(acc[1][jj], a1, b);
            fma2(acc[2][jj], a2, b);
            fma2(acc[3][jj], a3, b);
        }
    }
}

// score[c][d] = sum_w Am[c][w]*Bm[d][w]; write WS[d*65+c] = {s,s}
__device__ __forceinline__ void sc128p(const float* __restrict__ Am,
                                       const float* __restrict__ Bm,
                                       int o0, int tx, ull* WS){
    ull acc[4][4];
    #pragma unroll
    for (int i = 0; i < 4; i++)
        #pragma unroll
        for (int j = 0; j < 4; j++) acc[i][j] = 0ull;
    #pragma unroll 4
    for (int kp = 0; kp < 64; kp++) {
        ull a[4], b[4];
        #pragma unroll
        for (int i = 0; i < 4; i++)
            a[i] = *reinterpret_cast<const ull*>(Am + (o0+i)*BSTRIDE + 2*kp);
        #pragma unroll
        for (int j = 0; j < 4; j++)
            b[j] = *reinterpret_cast<const ull*>(Bm + (tx+16*j)*BSTRIDE + 2*kp);
        #pragma unroll
        for (int i = 0; i < 4; i++)
            #pragma unroll
            for (int j = 0; j < 4; j++) fma2(acc[i][j], a[i], b[j]);
    }
    #pragma unroll
    for (int i = 0; i < 4; i++)
        #pragma unroll
        for (int j = 0; j < 4; j++) {
            float lo, hi; unpk(acc[i][j], lo, hi);
            float s = lo + hi;
            WS[(tx+16*j)*WSTRIDE + o0 + i] = pk2(s, s);
        }
}

__global__ void __launch_bounds__(256, 1)
attn_kernel(const float* __restrict__ x,  const float* __restrict__ xf, const float* __restrict__ xr,
            const float* __restrict__ Wx,  const float* __restrict__ bx,
            const float* __restrict__ Wx1, const float* __restrict__ bx1,
            const float* __restrict__ Wx2, const float* __restrict__ bx2,
            const float* __restrict__ Wxf, const float* __restrict__ bxf,
            const float* __restrict__ Wxr, const float* __restrict__ bxr)
{
    extern __shared__ ull smu[];
    ull*   WS   = smu;                         // 64*65 ull
    float* BufA = (float*)(WS + 64*WSTRIDE);
    float* BufP = BufA + 64*BSTRIDE;
    float* BufF = BufP + 64*BSTRIDE;
    float* bst  = BufF + 64*BSTRIDE;

    const int tid = threadIdx.x;
    const int ty = tid >> 4, tx = tid & 15;
    const int o0 = ty*4;
    const int y = blockIdx.x, n = blockIdx.y;
    const int rowoff = n*CHW + y*WW;

    ull acc[4][4];

    // 1) xp = Wx@x + bx -> BufP
    load_row130(BufA, x + rowoff, tid);
    load_wdup(WS, bst, Wx, bx, tid);
    __syncthreads();
    mm64p(WS, BufA, o0, tx, acc);
    #pragma unroll
    for (int i = 0; i < 4; i++) {
        ull bb = pk2(bst[o0+i], bst[o0+i]);
        #pragma unroll
        for (int jj = 0; jj < 4; jj++)
            *reinterpret_cast<ull*>(BufP + (o0+i)*BSTRIDE + 2*tx + 32*jj) = add2(acc[i][jj], bb);
    }
    __syncthreads();

    // 2) xfp = Wxf@xf + bxf -> BufF (in place)
    load_row130(BufF, xf + rowoff, tid);
    load_wdup(WS, bst, Wxf, bxf, tid);
    __syncthreads();
    mm64p(WS, BufF, o0, tx, acc);
    __syncthreads();
    #pragma unroll
    for (int i = 0; i < 4; i++) {
        ull bb = pk2(bst[o0+i], bst[o0+i]);
        #pragma unroll
        for (int jj = 0; jj < 4; jj++)
            *reinterpret_cast<ull*>(BufF + (o0+i)*BSTRIDE + 2*tx + 32*jj) = add2(acc[i][jj], bb);
    }
    __syncthreads();

    // 3) x1 = Wx1@xp + bx1 -> BufA
    load_wdup(WS, bst, Wx1, bx1, tid);
    __syncthreads();
    mm64p(WS, BufP, o0, tx, acc);
    #pragma unroll
    for (int i = 0; i < 4; i++) {
        ull bb = pk2(bst[o0+i], bst[o0+i]);
        #pragma unroll
        for (int jj = 0; jj < 4; jj++)
            *reinterpret_cast<ull*>(BufA + (o0+i)*BSTRIDE + 2*tx + 32*jj) = add2(acc[i][jj], bb);
    }
    __syncthreads();

    // 4) score1 = x1 . xfp^T -> WS
    sc128p(BufA, BufF, o0, tx, WS);
    __syncthreads();

    // 5) featF = score1 @ xp -> global
    mm64p(WS, BufP, o0, tx, acc);
    #pragma unroll
    for (int i = 0; i < 4; i++)
        #pragma unroll
        for (int jj = 0; jj < 4; jj++)
            *reinterpret_cast<ull*>(&g_featF[rowoff + (o0+i)*HW + 2*tx + 32*jj]) = acc[i][jj];
    __syncthreads();

    // 6) xrp = Wxr@xr + bxr -> BufF (in place)
    load_row130(BufF, xr + rowoff, tid);
    load_wdup(WS, bst, Wxr, bxr, tid);
    __syncthreads();
    mm64p(WS, BufF, o0, tx, acc);
    __syncthreads();
    #pragma unroll
    for (int i = 0; i < 4; i++) {
        ull bb = pk2(bst[o0+i], bst[o0+i]);
        #pragma unroll
        for (int jj = 0; jj < 4; jj++)
            *reinterpret_cast<ull*>(BufF + (o0+i)*BSTRIDE + 2*tx + 32*jj) = add2(acc[i][jj], bb);
    }
    __syncthreads();

    // 7) x2 = Wx2@xp + bx2 -> BufA
    load_wdup(WS, bst, Wx2, bx2, tid);
    __syncthreads();
    mm64p(WS, BufP, o0, tx, acc);
    #pragma unroll
    for (int i = 0; i < 4; i++) {
        ull bb = pk2(bst[o0+i], bst[o0+i]);
        #pragma unroll
        for (int jj = 0; jj < 4; jj++)
            *reinterpret_cast<ull*>(BufA + (o0+i)*BSTRIDE + 2*tx + 32*jj) = add2(acc[i][jj], bb);
    }
    __syncthreads();

    // 8) score2 = x2 . xrp^T -> WS
    sc128p(BufA, BufF, o0, tx, WS);
    __syncthreads();

    // 9) featR = score2 @ xp -> global
    mm64p(WS, BufP, o0, tx, acc);
    #pragma unroll
    for (int i = 0; i < 4; i++)
        #pragma unroll
        for (int jj = 0; jj < 4; jj++)
            *reinterpret_cast<ull*>(&g_featR[rowoff + (o0+i)*HW + 2*tx + 32*jj]) = acc[i][jj];
}

// ---------------- conv kernel: 3x3, 192->192, + BN + ReLU ----------------
// block: 64 out-ch (ob) x 2 rows x 128 cols. 24 chunks of 8 in-channels.
// smem: As2 ull[72*67] duplicated weight pairs, Bs float[4*8*132]
#define CK   8
#define NCH  24
#define AST  67
#define BSTC 132
#define SMEM2_BYTES (72*AST*8 + 4*CK*BSTC*4)

__global__ void __launch_bounds__(256, 2)
conv_kernel(const float* __restrict__ x,     const float* __restrict__ Wmsa,
            const float* __restrict__ bmsa,  const float* __restrict__ gamma,
            const float* __restrict__ beta,  const float* __restrict__ mean,
            const float* __restrict__ var,   float* __restrict__ out)
{
    extern __shared__ ull smu[];
    ull*   As2 = smu;                    // [ (k*9+tap)*67 + o ]
    float* Bs  = (float*)(As2 + 72*AST); // [ (rr*8+k)*132 + col ], col = x+1

    const int tid = threadIdx.x;
    const int ty = tid >> 4, tx = tid & 15;
    const int o0 = ty*4;
    const int y0 = blockIdx.x*2, n = blockIdx.y, ob = blockIdx.z;

    ull acc[2][4][4];
    #pragma unroll
    for (int r = 0; r < 2; r++)
        #pragma unroll
        for (int i = 0; i < 4; i++)
            #pragma unroll
            for (int jj = 0; jj < 4; jj++) acc[r][i][jj] = 0ull;

    for (int chunk = 0; chunk < NCH; ++chunk) {
        __syncthreads();
        const int ci0 = chunk*CK;

        // weights: rem = k*9 + tap, contiguous 72-float span per o
        {
            const float* wb = Wmsa + (size_t)(ob*64)*1728 + ci0*9;
            for (int idx = tid; idx < 64*72; idx += 256) {
                int o = idx/72, rem = idx - o*72;
                float w = wb[(size_t)o*1728 + rem];
                As2[rem*AST + o] = pk2(w, w);
            }
        }
        // input rows y0-1 .. y0+2 for this channel chunk
        {
            const float* srcb;
            if      (ci0 < 64)  srcb = g_featF + (size_t)n*CHW + ci0*HW;
            else if (ci0 < 128) srcb = g_featR + (size_t)n*CHW + (ci0-64)*HW;
            else                srcb = x       + (size_t)n*CHW + (ci0-128)*HW;
            for (int idx = tid; idx < 4*CK*130; idx += 256) {
                int rr  = idx/(CK*130);
                int rem = idx - rr*(CK*130);
                int k   = rem/130, col = rem - k*130;
                int iy = y0 - 1 + rr, gx = col - 1;
                float v = 0.f;
                if (iy >= 0 && iy < HH && gx >= 0 && gx < WW)
                    v = srcb[k*HW + iy*WW + gx];
                Bs[(rr*CK + k)*BSTC + col] = v;
            }
        }
        __syncthreads();

        #pragma unroll 2
        for (int k = 0; k < CK; k++) {
            #pragma unroll
            for (int kh = 0; kh < 3; kh++) {
                ull aw[3][4];
                #pragma unroll
                for (int kw = 0; kw < 3; kw++)
                    #pragma unroll
                    for (int i = 0; i < 4; i++)
                        aw[kw][i] = As2[(k*9 + kh*3 + kw)*AST + o0 + i];
                #pragma unroll
                for (int r = 0; r < 2; r++) {
                    const float* rp = Bs + ((r+kh)*CK + k)*BSTC + 2*tx;
                    #pragma unroll
                    for (int jj = 0; jj < 4; jj++) {
                        ull v01 = *reinterpret_cast<const ull*>(rp + 32*jj);
                        ull v23 = *reinterpret_cast<const ull*>(rp + 32*jj + 2);
                        ull v12 = mid2(v01, v23);
                        #pragma unroll
                        for (int i = 0; i < 4; i++) {
                            fma2(acc[r][i][jj], aw[0][i], v01);
                            fma2(acc[r][i][jj], aw[1][i], v12);
                            fma2(acc[r][i][jj], aw[2][i], v23);
                        }
                    }
                }
            }
        }
    }

    // epilogue: bias + BN(eval) + ReLU, float2 stores
    #pragma unroll
    for (int i = 0; i < 4; i++) {
        const int o = ob*64 + o0 + i;
        const float s  = gamma[o] * rsqrtf(var[o] + 1e-4f);
        const float t0 = (bmsa[o] - mean[o]) * s + beta[o];
        #pragma unroll
        for (int r = 0; r < 2; r++) {
            float* orow = out + ((size_t)(n*192 + o)*HH + (y0 + r))*WW;
            #pragma unroll
            for (int jj = 0; jj < 4; jj++) {
                float lo, hi; unpk(acc[r][i][jj], lo, hi);
                float v0 = fmaxf(fmaf(lo, s, t0), 0.f);
                float v1 = fmaxf(fmaf(hi, s, t0), 0.f);
                *reinterpret_cast<ull*>(orow + 2*tx + 32*jj) = pk2(v0, v1);
            }
        }
    }
}

// ---------------- launch ----------------

extern "C" void kernel_launch(void* const* d_in, const int* in_sizes, int n_in,
                              void* d_out, int out_size)
{
    const float* x    = (const float*)d_in[0];
    const float* xf   = (const float*)d_in[1];
    const float* xr   = (const float*)d_in[2];
    const float* Wx   = (const float*)d_in[3];
    const float* bx   = (const float*)d_in[4];
    const float* Wx1  = (const float*)d_in[5];
    const float* bx1  = (const float*)d_in[6];
    const float* Wx2  = (const float*)d_in[7];
    const float* bx2  = (const float*)d_in[8];
    const float* Wxf  = (const float*)d_in[9];
    const float* bxf  = (const float*)d_in[10];
    const float* Wxr  = (const float*)d_in[11];
    const float* bxr  = (const float*)d_in[12];
    const float* Wmsa = (const float*)d_in[13];
    const float* bmsa = (const float*)d_in[14];
    const float* gam  = (const float*)d_in[15];
    const float* bet  = (const float*)d_in[16];
    const float* mu   = (const float*)d_in[17];
    const float* var  = (const float*)d_in[18];
    float* out = (float*)d_out;

    cudaFuncSetAttribute(attn_kernel, cudaFuncAttributeMaxDynamicSharedMemorySize, SMEM1_BYTES);
    cudaFuncSetAttribute(conv_kernel, cudaFuncAttributeMaxDynamicSharedMemorySize, SMEM2_BYTES);

    dim3 g1(HH, BB);
    attn_kernel<<<g1, 256, SMEM1_BYTES>>>(x, xf, xr, Wx, bx, Wx1, bx1, Wx2, bx2,
                                          Wxf, bxf, Wxr, bxr);

    dim3 g2(HH/2, BB, 3);
    conv_kernel<<<g2, 256, SMEM2_BYTES>>>(x, Wmsa, bmsa, gam, bet, mu, var, out);
}

// round 9
// speedup vs baseline: 2.3395x; 1.4097x over previous
#include <cuda_runtime.h>
#include <cuda_bf16.h>
#include <cstdint>

typedef unsigned long long ull;

#define CC   64
#define HH   128
#define WW   128
#define BB   8
#define HW   (HH*WW)        // 16384
#define CHW  (CC*HW)        // 1048576

// scratch
__device__ float g_featF[BB*CC*HH*WW];
__device__ float g_featR[BB*CC*HH*WW];
// pre-split conv weights: [slot54][o192][ci32] ushort; slot = (kh*3+kw)*6+cg
__device__ unsigned short g_Wh[54*192*32];
__device__ unsigned short g_Wl[54*192*32];

// ---------------- f32x2 helpers (attn kernel) ----------------
__device__ __forceinline__ ull pk2(float lo, float hi){
    ull r; asm("mov.b64 %0, {%1,%2};" : "=l"(r) : "f"(lo), "f"(hi)); return r;
}
__device__ __forceinline__ void unpk(ull a, float& lo, float& hi){
    asm("mov.b64 {%0,%1}, %2;" : "=f"(lo), "=f"(hi) : "l"(a));
}
__device__ __forceinline__ void fma2(ull& d, ull a, ull b){
    asm("fma.rn.f32x2 %0, %1, %2, %0;" : "+l"(d) : "l"(a), "l"(b));
}
__device__ __forceinline__ ull add2(ull a, ull b){
    ull r; asm("add.rn.f32x2 %0, %1, %2;" : "=l"(r) : "l"(a), "l"(b)); return r;
}

// ---------------- misc helpers ----------------
__device__ __forceinline__ uint32_t smem_u32(const void* p){
    uint32_t a;
    asm("{ .reg .u64 t; cvta.to.shared.u64 t, %1; cvt.u32.u64 %0, t; }" : "=r"(a) : "l"(p));
    return a;
}
__device__ __forceinline__ void cp_async8(uint32_t dst, const void* src){
    asm volatile("cp.async.ca.shared.global [%0], [%1], 8;" :: "r"(dst), "l"(src) : "memory");
}
__device__ __forceinline__ void cp_commit(){ asm volatile("cp.async.commit_group;" ::: "memory"); }
__device__ __forceinline__ void cp_wait0(){ asm volatile("cp.async.wait_group 0;" ::: "memory"); }

__device__ __forceinline__ void bsplit(float v, unsigned short& h, unsigned short& l){
    __nv_bfloat16 hb = __float2bfloat16(v);
    float r = v - __bfloat162float(hb);
    __nv_bfloat16 lb = __float2bfloat16(r);
    h = __bfloat16_as_ushort(hb); l = __bfloat16_as_ushort(lb);
}

__device__ __forceinline__ void mma16816(float* d, const uint32_t* a, uint32_t b0, uint32_t b1){
    asm volatile(
        "mma.sync.aligned.m16n8k16.row.col.f32.bf16.bf16.f32 "
        "{%0,%1,%2,%3}, {%4,%5,%6,%7}, {%8,%9}, {%0,%1,%2,%3};"
        : "+f"(d[0]), "+f"(d[1]), "+f"(d[2]), "+f"(d[3])
        : "r"(a[0]), "r"(a[1]), "r"(a[2]), "r"(a[3]), "r"(b0), "r"(b1));
}

// ---------------- weight prep ----------------
__global__ void wprep_kernel(const float* __restrict__ Wmsa)
{
    int slot = blockIdx.x;              // (kh*3+kw)*6 + cg
    int tap = slot / 6, cg = slot % 6;
    for (int idx = threadIdx.x; idx < 6144; idx += 256) {
        int o = idx >> 5, cil = idx & 31;
        int ci = cg*32 + cil;
        float w = Wmsa[(size_t)o*1728 + ci*9 + tap];
        unsigned short h, l; bsplit(w, h, l);
        g_Wh[(size_t)slot*6144 + idx] = h;
        g_Wl[(size_t)slot*6144 + idx] = l;
    }
}

// ---------------- attn kernel (unchanged, proven) ----------------
#define BSTRIDE 130
#define WSTRIDE 65
#define SMEM1_BYTES (64*WSTRIDE*8 + 3*64*BSTRIDE*4 + 64*4)

__device__ __forceinline__ void load_row130(float* dst, const float* src, int tid){
    for (int idx = tid; idx < 64*128; idx += 256) {
        int c = idx >> 7, xx = idx & 127;
        dst[c*BSTRIDE + xx] = src[c*HW + xx];
    }
}
__device__ __forceinline__ void load_wdup(ull* WS, float* bst,
                                          const float* Wg, const float* bg, int tid){
    for (int idx = tid; idx < 4096; idx += 256) {
        int o = idx >> 6, k = idx & 63;
        float w = Wg[idx];
        WS[k*WSTRIDE + o] = pk2(w, w);
    }
    if (tid < 64) bst[tid] = bg[tid];
}
__device__ __forceinline__ void mm64p(const ull* __restrict__ A2,
                                      const float* __restrict__ Bm,
                                      int o0, int tx, ull acc[4][4]){
    #pragma unroll
    for (int i = 0; i < 4; i++)
        #pragma unroll
        for (int j = 0; j < 4; j++) acc[i][j] = 0ull;
    #pragma unroll 4
    for (int k = 0; k < 64; k++) {
        ull a0 = A2[k*WSTRIDE + o0    ];
        ull a1 = A2[k*WSTRIDE + o0 + 1];
        ull a2 = A2[k*WSTRIDE + o0 + 2];
        ull a3 = A2[k*WSTRIDE + o0 + 3];
        const float* bp = Bm + k*BSTRIDE + 2*tx;
        #pragma unroll
        for (int jj = 0; jj < 4; jj++) {
            ull b = *reinterpret_cast<const ull*>(bp + 32*jj);
            fma2(acc[0][jj], a0, b);
            fma2(acc[1][jj], a1, b);
            fma2(acc[2][jj], a2, b);
            fma2(acc[3][jj], a3, b);
        }
    }
}
__device__ __forceinline__ void sc128p(const float* __restrict__ Am,
                                       const float* __restrict__ Bm,
                                       int o0, int tx, ull* WS){
    ull acc[4][4];
    #pragma unroll
    for (int i = 0; i < 4; i++)
        #pragma unroll
        for (int j = 0; j < 4; j++) acc[i][j] = 0ull;
    #pragma unroll 4
    for (int kp = 0; kp < 64; kp++) {
        ull a[4], b[4];
        #pragma unroll
        for (int i = 0; i < 4; i++)
            a[i] = *reinterpret_cast<const ull*>(Am + (o0+i)*BSTRIDE + 2*kp);
        #pragma unroll
        for (int j = 0; j < 4; j++)
            b[j] = *reinterpret_cast<const ull*>(Bm + (tx+16*j)*BSTRIDE + 2*kp);
        #pragma unroll
        for (int i = 0; i < 4; i++)
            #pragma unroll
            for (int j = 0; j < 4; j++) fma2(acc[i][j], a[i], b[j]);
    }
    #pragma unroll
    for (int i = 0; i < 4; i++)
        #pragma unroll
        for (int j = 0; j < 4; j++) {
            float lo, hi; unpk(acc[i][j], lo, hi);
            float s = lo + hi;
            WS[(tx+16*j)*WSTRIDE + o0 + i] = pk2(s, s);
        }
}

__global__ void __launch_bounds__(256, 1)
attn_kernel(const float* __restrict__ x,  const float* __restrict__ xf, const float* __restrict__ xr,
            const float* __restrict__ Wx,  const float* __restrict__ bx,
            const float* __restrict__ Wx1, const float* __restrict__ bx1,
            const float* __restrict__ Wx2, const float* __restrict__ bx2,
            const float* __restrict__ Wxf, const float* __restrict__ bxf,
            const float* __restrict__ Wxr, const float* __restrict__ bxr)
{
    extern __shared__ ull smu[];
    ull*   WS   = smu;
    float* BufA = (float*)(WS + 64*WSTRIDE);
    float* BufP = BufA + 64*BSTRIDE;
    float* BufF = BufP + 64*BSTRIDE;
    float* bst  = BufF + 64*BSTRIDE;

    const int tid = threadIdx.x;
    const int ty = tid >> 4, tx = tid & 15;
    const int o0 = ty*4;
    const int y = blockIdx.x, n = blockIdx.y;
    const int rowoff = n*CHW + y*WW;

    ull acc[4][4];

    load_row130(BufA, x + rowoff, tid);
    load_wdup(WS, bst, Wx, bx, tid);
    __syncthreads();
    mm64p(WS, BufA, o0, tx, acc);
    #pragma unroll
    for (int i = 0; i < 4; i++) {
        ull bb = pk2(bst[o0+i], bst[o0+i]);
        #pragma unroll
        for (int jj = 0; jj < 4; jj++)
            *reinterpret_cast<ull*>(BufP + (o0+i)*BSTRIDE + 2*tx + 32*jj) = add2(acc[i][jj], bb);
    }
    __syncthreads();

    load_row130(BufF, xf + rowoff, tid);
    load_wdup(WS, bst, Wxf, bxf, tid);
    __syncthreads();
    mm64p(WS, BufF, o0, tx, acc);
    __syncthreads();
    #pragma unroll
    for (int i = 0; i < 4; i++) {
        ull bb = pk2(bst[o0+i], bst[o0+i]);
        #pragma unroll
        for (int jj = 0; jj < 4; jj++)
            *reinterpret_cast<ull*>(BufF + (o0+i)*BSTRIDE + 2*tx + 32*jj) = add2(acc[i][jj], bb);
    }
    __syncthreads();

    load_wdup(WS, bst, Wx1, bx1, tid);
    __syncthreads();
    mm64p(WS, BufP, o0, tx, acc);
    #pragma unroll
    for (int i = 0; i < 4; i++) {
        ull bb = pk2(bst[o0+i], bst[o0+i]);
        #pragma unroll
        for (int jj = 0; jj < 4; jj++)
            *reinterpret_cast<ull*>(BufA + (o0+i)*BSTRIDE + 2*tx + 32*jj) = add2(acc[i][jj], bb);
    }
    __syncthreads();

    sc128p(BufA, BufF, o0, tx, WS);
    __syncthreads();

    mm64p(WS, BufP, o0, tx, acc);
    #pragma unroll
    for (int i = 0; i < 4; i++)
        #pragma unroll
        for (int jj = 0; jj < 4; jj++)
            *reinterpret_cast<ull*>(&g_featF[rowoff + (o0+i)*HW + 2*tx + 32*jj]) = acc[i][jj];
    __syncthreads();

    load_row130(BufF, xr + rowoff, tid);
    load_wdup(WS, bst, Wxr, bxr, tid);
    __syncthreads();
    mm64p(WS, BufF, o0, tx, acc);
    __syncthreads();
    #pragma unroll
    for (int i = 0; i < 4; i++) {
        ull bb = pk2(bst[o0+i], bst[o0+i]);
        #pragma unroll
        for (int jj = 0; jj < 4; jj++)
            *reinterpret_cast<ull*>(BufF + (o0+i)*BSTRIDE + 2*tx + 32*jj) = add2(acc[i][jj], bb);
    }
    __syncthreads();

    load_wdup(WS, bst, Wx2, bx2, tid);
    __syncthreads();
    mm64p(WS, BufP, o0, tx, acc);
    #pragma unroll
    for (int i = 0; i < 4; i++) {
        ull bb = pk2(bst[o0+i], bst[o0+i]);
        #pragma unroll
        for (int jj = 0; jj < 4; jj++)
            *reinterpret_cast<ull*>(BufA + (o0+i)*BSTRIDE + 2*tx + 32*jj) = add2(acc[i][jj], bb);
    }
    __syncthreads();

    sc128p(BufA, BufF, o0, tx, WS);
    __syncthreads();

    mm64p(WS, BufP, o0, tx, acc);
    #pragma unroll
    for (int i = 0; i < 4; i++)
        #pragma unroll
        for (int jj = 0; jj < 4; jj++)
            *reinterpret_cast<ull*>(&g_featR[rowoff + (o0+i)*HW + 2*tx + 32*jj]) = acc[i][jj];
}

// ---------------- conv kernel: mma.sync bf16 implicit GEMM ----------------
// block=(y,n): out 192 o x 128 x. 18 stages (kh 0..2, cg 0..5 of 32 ci).
// smem buffer: A tiles [kw(3)][h/l(2)][192 o][32 k pad->36] ushort = 6*13824B,
//              Bh [132 rows(x+1) pad][32 k pad->36] ushort = 9504B, Bl same.
#define A_TILE_B  13824     // 192*72
#define A_BYTES   82944     // 6 tiles
#define BH_OFF    82944
#define BL_OFF    92448
#define BUF_BYTES 101952
#define CONV_SMEM (2*BUF_BYTES)

__device__ __forceinline__ void conv_fillB(char* Bbuf, int s, int n, int y,
                                           const float* __restrict__ x, int tid)
{
    const int kh = s/6, cg = s - (s/6)*6;
    const int ci0 = cg*32;
    const float* srcb;
    if      (ci0 < 64)  srcb = g_featF + (size_t)n*CHW + ci0*HW;
    else if (ci0 < 128) srcb = g_featR + (size_t)n*CHW + (ci0-64)*HW;
    else                srcb = x       + (size_t)n*CHW + (ci0-128)*HW;
    const int iy = y - 1 + kh;
    const bool vrow = (iy >= 0 && iy < HH);
    for (int idx = tid; idx < 32*130; idx += 256) {
        int ci = idx / 130, col = idx - ci*130;
        int gx = col - 1;
        float v = 0.f;
        if (vrow && gx >= 0 && gx < WW) v = srcb[(size_t)ci*HW + iy*WW + gx];
        unsigned short h, l; bsplit(v, h, l);
        reinterpret_cast<unsigned short*>(Bbuf + BH_OFF + col*72)[ci] = h;
        reinterpret_cast<unsigned short*>(Bbuf + BL_OFF - BH_OFF + BH_OFF + 9504*0 + 0)[0] = reinterpret_cast<unsigned short*>(Bbuf + BL_OFF + col*72)[ci] = l;
    }
}

__device__ __forceinline__ void conv_issueA(uint32_t dst_base, int s, int tid)
{
    const int kh = s/6, cg = s - (s/6)*6;
    for (int q = tid; q < 9216; q += 256) {
        int t   = q / 1536;            // kw*2 + hl
        int rem = q - t*1536;
        int o   = rem >> 3, k8 = rem & 7;
        int kw  = t >> 1,   hl = t & 1;
        int slot = (kh*3 + kw)*6 + cg;
        const unsigned short* src = (hl ? g_Wl : g_Wh) + (size_t)slot*6144 + o*32 + k8*4;
        cp_async8(dst_base + t*A_TILE_B + o*72 + k8*8, src);
    }
}

__global__ void __launch_bounds__(256, 1)
conv_mma_kernel(const float* __restrict__ x,
                const float* __restrict__ bmsa, const float* __restrict__ gamma,
                const float* __restrict__ beta, const float* __restrict__ mean,
                const float* __restrict__ var,  float* __restrict__ out)
{
    extern __shared__ char smem[];
    const uint32_t smem_base = smem_u32(smem);
    const int tid  = threadIdx.x;
    const int lane = tid & 31, wid = tid >> 5;
    const int wm2 = wid >> 2;          // 0..1 -> M offset 96*wm2
    const int wn2 = wid & 3;           // 0..3 -> N offset 32*wn2
    const int y = blockIdx.x, n = blockIdx.y;

    float acc[6][4][4];
    #pragma unroll
    for (int mi = 0; mi < 6; mi++)
        #pragma unroll
        for (int nb = 0; nb < 4; nb++)
            #pragma unroll
            for (int e = 0; e < 4; e++) acc[mi][nb][e] = 0.f;

    // prologue: stage 0
    conv_issueA(smem_base, 0, tid);
    cp_commit();
    conv_fillB(smem, 0, n, y, x, tid);

    for (int s = 0; s < 18; s++) {
        const int b = s & 1;
        char* buf = smem + b*BUF_BYTES;

        cp_wait0();
        __syncthreads();

        if (s < 17) { conv_issueA(smem_base + (b^1)*BUF_BYTES, s+1, tid); cp_commit(); }

        // ---- compute stage s ----
        const char* Ab = buf;
        const char* Bh = buf + BH_OFF;
        const char* Bl = buf + BL_OFF;
        const int acol = (lane & 3) * 4;
        const int arow = wm2*96 + (lane >> 2);
        const int brow0 = wn2*32 + (lane >> 2);

        #pragma unroll
        for (int kw = 0; kw < 3; kw++) {
            const char* Ah = Ab + (kw*2 + 0)*A_TILE_B;
            const char* Al = Ab + (kw*2 + 1)*A_TILE_B;
            #pragma unroll
            for (int ks = 0; ks < 2; ks++) {
                const int koff = ks*32 + acol;
                uint32_t aF[6][4];
                // Ah frags
                #pragma unroll
                for (int mi = 0; mi < 6; mi++) {
                    const char* p = Ah + (arow + mi*16)*72 + koff;
                    aF[mi][0] = *reinterpret_cast<const uint32_t*>(p);
                    aF[mi][1] = *reinterpret_cast<const uint32_t*>(p + 8*72);
                    aF[mi][2] = *reinterpret_cast<const uint32_t*>(p + 16);
                    aF[mi][3] = *reinterpret_cast<const uint32_t*>(p + 8*72 + 16);
                }
                // Ah*Bh, Ah*Bl
                #pragma unroll
                for (int bs = 0; bs < 2; bs++) {
                    const char* Bp = bs ? Bl : Bh;
                    #pragma unroll
                    for (int nb = 0; nb < 4; nb++) {
                        const char* q = Bp + (brow0 + nb*8 + kw)*72 + koff;
                        uint32_t b0 = *reinterpret_cast<const uint32_t*>(q);
                        uint32_t b1 = *reinterpret_cast<const uint32_t*>(q + 16);
                        #pragma unroll
                        for (int mi = 0; mi < 6; mi++)
                            mma16816(acc[mi][nb], aF[mi], b0, b1);
                    }
                }
                // Al frags, Al*Bh
                #pragma unroll
                for (int mi = 0; mi < 6; mi++) {
                    const char* p = Al + (arow + mi*16)*72 + koff;
                    aF[mi][0] = *reinterpret_cast<const uint32_t*>(p);
                    aF[mi][1] = *reinterpret_cast<const uint32_t*>(p + 8*72);
                    aF[mi][2] = *reinterpret_cast<const uint32_t*>(p + 16);
                    aF[mi][3] = *reinterpret_cast<const uint32_t*>(p + 8*72 + 16);
                }
                #pragma unroll
                for (int nb = 0; nb < 4; nb++) {
                    const char* q = Bh + (brow0 + nb*8 + kw)*72 + koff;
                    uint32_t b0 = *reinterpret_cast<const uint32_t*>(q);
                    uint32_t b1 = *reinterpret_cast<const uint32_t*>(q + 16);
                    #pragma unroll
                    for (int mi = 0; mi < 6; mi++)
                        mma16816(acc[mi][nb], aF[mi], b0, b1);
                }
            }
        }

        if (s < 17) conv_fillB(smem + (b^1)*BUF_BYTES, s+1, n, y, x, tid);
    }

    // ---- epilogue: bias + BN + ReLU, direct float2 stores ----
    #pragma unroll
    for (int mi = 0; mi < 6; mi++) {
        #pragma unroll
        for (int h = 0; h < 2; h++) {
            const int o = wm2*96 + mi*16 + (lane >> 2) + h*8;
            const float sc = gamma[o] * rsqrtf(var[o] + 1e-4f);
            const float t0 = (bmsa[o] - mean[o]) * sc + beta[o];
            float* orow = out + (((size_t)n*192 + o)*HH + y)*WW;
            #pragma unroll
            for (int nb = 0; nb < 4; nb++) {
                const int x0 = wn2*32 + nb*8 + (lane & 3)*2;
                float v0 = fmaxf(fmaf(acc[mi][nb][h*2+0], sc, t0), 0.f);
                float v1 = fmaxf(fmaf(acc[mi][nb][h*2+1], sc, t0), 0.f);
                *reinterpret_cast<ull*>(orow + x0) = pk2(v0, v1);
            }
        }
    }
}

// ---------------- launch ----------------
extern "C" void kernel_launch(void* const* d_in, const int* in_sizes, int n_in,
                              void* d_out, int out_size)
{
    const float* x    = (const float*)d_in[0];
    const float* xf   = (const float*)d_in[1];
    const float* xr   = (const float*)d_in[2];
    const float* Wx   = (const float*)d_in[3];
    const float* bx   = (const float*)d_in[4];
    const float* Wx1  = (const float*)d_in[5];
    const float* bx1  = (const float*)d_in[6];
    const float* Wx2  = (const float*)d_in[7];
    const float* bx2  = (const float*)d_in[8];
    const float* Wxf  = (const float*)d_in[9];
    const float* bxf  = (const float*)d_in[10];
    const float* Wxr  = (const float*)d_in[11];
    const float* bxr  = (const float*)d_in[12];
    const float* Wmsa = (const float*)d_in[13];
    const float* bmsa = (const float*)d_in[14];
    const float* gam  = (const float*)d_in[15];
    const float* bet  = (const float*)d_in[16];
    const float* mu   = (const float*)d_in[17];
    const float* var  = (const float*)d_in[18];
    float* out = (float*)d_out;

    cudaFuncSetAttribute(attn_kernel, cudaFuncAttributeMaxDynamicSharedMemorySize, SMEM1_BYTES);
    cudaFuncSetAttribute(conv_mma_kernel, cudaFuncAttributeMaxDynamicSharedMemorySize, CONV_SMEM);

    wprep_kernel<<<54, 256>>>(Wmsa);

    dim3 g1(HH, BB);
    attn_kernel<<<g1, 256, SMEM1_BYTES>>>(x, xf, xr, Wx, bx, Wx1, bx1, Wx2, bx2,
                                          Wxf, bxf, Wxr, bxr);

    dim3 g2(HH, BB);
    conv_mma_kernel<<<g2, 256, CONV_SMEM>>>(x, bmsa, gam, bet, mu, var, out);
}

// round 11
// speedup vs baseline: 4.1872x; 1.7898x over previous
#include <cuda_runtime.h>
#include <cuda_bf16.h>
#include <cstdint>

typedef unsigned long long ull;

#define CC   64
#define HH   128
#define WW   128
#define BB   8
#define HW   (HH*WW)        // 16384
#define CHW  (CC*HW)        // 1048576

// pre-split, pre-transposed planes: ushort [n][y][x][ci(64)]
__device__ unsigned short g_featFH[BB*HH*WW*64];
__device__ unsigned short g_featFL[BB*HH*WW*64];
__device__ unsigned short g_featRH[BB*HH*WW*64];
__device__ unsigned short g_featRL[BB*HH*WW*64];
__device__ unsigned short g_xH[BB*HH*WW*64];
__device__ unsigned short g_xL[BB*HH*WW*64];
// pre-split conv weights: [slot54][o192][ci32] ushort; slot = (kh*3+kw)*6+cg
__device__ unsigned short g_Wh[54*192*32];
__device__ unsigned short g_Wl[54*192*32];

// ---------------- f32x2 helpers ----------------
__device__ __forceinline__ ull pk2(float lo, float hi){
    ull r; asm("mov.b64 %0, {%1,%2};" : "=l"(r) : "f"(lo), "f"(hi)); return r;
}
__device__ __forceinline__ void unpk(ull a, float& lo, float& hi){
    asm("mov.b64 {%0,%1}, %2;" : "=f"(lo), "=f"(hi) : "l"(a));
}
__device__ __forceinline__ void fma2(ull& d, ull a, ull b){
    asm("fma.rn.f32x2 %0, %1, %2, %0;" : "+l"(d) : "l"(a), "l"(b));
}
__device__ __forceinline__ ull add2(ull a, ull b){
    ull r; asm("add.rn.f32x2 %0, %1, %2;" : "=l"(r) : "l"(a), "l"(b)); return r;
}

// ---------------- misc helpers ----------------
__device__ __forceinline__ uint32_t smem_u32(const void* p){
    uint32_t a;
    asm("{ .reg .u64 t; cvta.to.shared.u64 t, %1; cvt.u32.u64 %0, t; }" : "=r"(a) : "l"(p));
    return a;
}
__device__ __forceinline__ void cp_async16(uint32_t dst, const void* src, int szbytes){
    asm volatile("cp.async.cg.shared.global [%0], [%1], 16, %2;"
                 :: "r"(dst), "l"(src), "r"(szbytes) : "memory");
}
__device__ __forceinline__ void cp_commit(){ asm volatile("cp.async.commit_group;" ::: "memory"); }
__device__ __forceinline__ void cp_wait0(){ asm volatile("cp.async.wait_group 0;" ::: "memory"); }

__device__ __forceinline__ void bsplit(float v, unsigned short& h, unsigned short& l){
    __nv_bfloat16 hb = __float2bfloat16(v);
    float r = v - __bfloat162float(hb);
    __nv_bfloat16 lb = __float2bfloat16(r);
    h = __bfloat16_as_ushort(hb); l = __bfloat16_as_ushort(lb);
}

__device__ __forceinline__ void mma16816(float* d, const uint32_t* a, uint32_t b0, uint32_t b1){
    asm volatile(
        "mma.sync.aligned.m16n8k16.row.col.f32.bf16.bf16.f32 "
        "{%0,%1,%2,%3}, {%4,%5,%6,%7}, {%8,%9}, {%0,%1,%2,%3};"
        : "+f"(d[0]), "+f"(d[1]), "+f"(d[2]), "+f"(d[3])
        : "r"(a[0]), "r"(a[1]), "r"(a[2]), "r"(a[3]), "r"(b0), "r"(b1));
}

// ---------------- weight prep ----------------
__global__ void wprep_kernel(const float* __restrict__ Wmsa)
{
    int slot = blockIdx.x;              // (kh*3+kw)*6 + cg
    int tap = slot / 6, cg = slot % 6;
    for (int idx = threadIdx.x; idx < 6144; idx += 256) {
        int o = idx >> 5, cil = idx & 31;
        int ci = cg*32 + cil;
        float w = Wmsa[(size_t)o*1728 + ci*9 + tap];
        unsigned short h, l; bsplit(w, h, l);
        g_Wh[(size_t)slot*6144 + idx] = h;
        g_Wl[(size_t)slot*6144 + idx] = l;
    }
}

// ---------------- x prep: NCHW float -> [n][y][x][c] split planes ----------------
__global__ void xprep_kernel(const float* __restrict__ x)
{
    __shared__ float row[64*130];
    const int y = blockIdx.x, n = blockIdx.y;
    const int tid = threadIdx.x;
    const float* src = x + (size_t)n*CHW + y*WW;
    for (int idx = tid; idx < 64*128; idx += 256) {
        int c = idx >> 7, xx = idx & 127;
        row[c*130 + xx] = src[(size_t)c*HW + xx];
    }
    __syncthreads();
    // thread handles (xx, c-group of 4)
    for (int idx = tid; idx < 128*16; idx += 256) {
        int xx = idx >> 4, c0 = (idx & 15)*4;
        ushort4 h4, l4;
        unsigned short h, l;
        bsplit(row[(c0+0)*130 + xx], h, l); h4.x = h; l4.x = l;
        bsplit(row[(c0+1)*130 + xx], h, l); h4.y = h; l4.y = l;
        bsplit(row[(c0+2)*130 + xx], h, l); h4.z = h; l4.z = l;
        bsplit(row[(c0+3)*130 + xx], h, l); h4.w = h; l4.w = l;
        size_t base = (((size_t)n*HH + y)*WW + xx)*64 + c0;
        *reinterpret_cast<ushort4*>(&g_xH[base]) = h4;
        *reinterpret_cast<ushort4*>(&g_xL[base]) = l4;
    }
}

// ---------------- attn kernel ----------------
#define BSTRIDE 130
#define WSTRIDE 65
#define SMEM1_BYTES (64*WSTRIDE*8 + 3*64*BSTRIDE*4 + 64*4)

__device__ __forceinline__ void load_row130(float* dst, const float* src, int tid){
    for (int idx = tid; idx < 64*128; idx += 256) {
        int c = idx >> 7, xx = idx & 127;
        dst[c*BSTRIDE + xx] = src[c*HW + xx];
    }
}
__device__ __forceinline__ void load_wdup(ull* WS, float* bst,
                                          const float* Wg, const float* bg, int tid){
    for (int idx = tid; idx < 4096; idx += 256) {
        int o = idx >> 6, k = idx & 63;
        float w = Wg[idx];
        WS[k*WSTRIDE + o] = pk2(w, w);
    }
    if (tid < 64) bst[tid] = bg[tid];
}
__device__ __forceinline__ void mm64p(const ull* __restrict__ A2,
                                      const float* __restrict__ Bm,
                                      int o0, int tx, ull acc[4][4]){
    #pragma unroll
    for (int i = 0; i < 4; i++)
        #pragma unroll
        for (int j = 0; j < 4; j++) acc[i][j] = 0ull;
    #pragma unroll 4
    for (int k = 0; k < 64; k++) {
        ull a0 = A2[k*WSTRIDE + o0    ];
        ull a1 = A2[k*WSTRIDE + o0 + 1];
        ull a2 = A2[k*WSTRIDE + o0 + 2];
        ull a3 = A2[k*WSTRIDE + o0 + 3];
        const float* bp = Bm + k*BSTRIDE + 2*tx;
        #pragma unroll
        for (int jj = 0; jj < 4; jj++) {
            ull b = *reinterpret_cast<const ull*>(bp + 32*jj);
            fma2(acc[0][jj], a0, b);
            fma2(acc[1][jj], a1, b);
            fma2(acc[2][jj], a2, b);
            fma2(acc[3][jj], a3, b);
        }
    }
}
__device__ __forceinline__ void sc128p(const float* __restrict__ Am,
                                       const float* __restrict__ Bm,
                                       int o0, int tx, ull* WS){
    ull acc[4][4];
    #pragma unroll
    for (int i = 0; i < 4; i++)
        #pragma unroll
        for (int j = 0; j < 4; j++) acc[i][j] = 0ull;
    #pragma unroll 4
    for (int kp = 0; kp < 64; kp++) {
        ull a[4], b[4];
        #pragma unroll
        for (int i = 0; i < 4; i++)
            a[i] = *reinterpret_cast<const ull*>(Am + (o0+i)*BSTRIDE + 2*kp);
        #pragma unroll
        for (int j = 0; j < 4; j++)
            b[j] = *reinterpret_cast<const ull*>(Bm + (tx+16*j)*BSTRIDE + 2*kp);
        #pragma unroll
        for (int i = 0; i < 4; i++)
            #pragma unroll
            for (int j = 0; j < 4; j++) fma2(acc[i][j], a[i], b[j]);
    }
    #pragma unroll
    for (int i = 0; i < 4; i++)
        #pragma unroll
        for (int j = 0; j < 4; j++) {
            float lo, hi; unpk(acc[i][j], lo, hi);
            float s = lo + hi;
            WS[(tx+16*j)*WSTRIDE + o0 + i] = pk2(s, s);
        }
}

// store acc (feature values) as split planes at [n][y][x][ci]
__device__ __forceinline__ void store_feat_planes(
    unsigned short* __restrict__ gH, unsigned short* __restrict__ gL,
    ull acc[4][4], int n, int y, int o0, int tx)
{
    #pragma unroll
    for (int jj = 0; jj < 4; jj++) {
        float lo[4], hi[4];
        #pragma unroll
        for (int i = 0; i < 4; i++) unpk(acc[i][jj], lo[i], hi[i]);
        #pragma unroll
        for (int e = 0; e < 2; e++) {
            int xx = 2*tx + 32*jj + e;
            ushort4 h4, l4;
            unsigned short h, l;
            bsplit(e ? hi[0] : lo[0], h, l); h4.x = h; l4.x = l;
            bsplit(e ? hi[1] : lo[1], h, l); h4.y = h; l4.y = l;
            bsplit(e ? hi[2] : lo[2], h, l); h4.z = h; l4.z = l;
            bsplit(e ? hi[3] : lo[3], h, l); h4.w = h; l4.w = l;
            size_t base = (((size_t)n*HH + y)*WW + xx)*64 + o0;
            *reinterpret_cast<ushort4*>(&gH[base]) = h4;
            *reinterpret_cast<ushort4*>(&gL[base]) = l4;
        }
    }
}

__global__ void __launch_bounds__(256, 1)
attn_kernel(const float* __restrict__ x,  const float* __restrict__ xf, const float* __restrict__ xr,
            const float* __restrict__ Wx,  const float* __restrict__ bx,
            const float* __restrict__ Wx1, const float* __restrict__ bx1,
            const float* __restrict__ Wx2, const float* __restrict__ bx2,
            const float* __restrict__ Wxf, const float* __restrict__ bxf,
            const float* __restrict__ Wxr, const float* __restrict__ bxr)
{
    extern __shared__ ull smu[];
    ull*   WS   = smu;
    float* BufA = (float*)(WS + 64*WSTRIDE);
    float* BufP = BufA + 64*BSTRIDE;
    float* BufF = BufP + 64*BSTRIDE;
    float* bst  = BufF + 64*BSTRIDE;

    const int tid = threadIdx.x;
    const int ty = tid >> 4, tx = tid & 15;
    const int o0 = ty*4;
    const int y = blockIdx.x, n = blockIdx.y;
    const int rowoff = n*CHW + y*WW;

    ull acc[4][4];

    load_row130(BufA, x + rowoff, tid);
    load_wdup(WS, bst, Wx, bx, tid);
    __syncthreads();
    mm64p(WS, BufA, o0, tx, acc);
    #pragma unroll
    for (int i = 0; i < 4; i++) {
        ull bb = pk2(bst[o0+i], bst[o0+i]);
        #pragma unroll
        for (int jj = 0; jj < 4; jj++)
            *reinterpret_cast<ull*>(BufP + (o0+i)*BSTRIDE + 2*tx + 32*jj) = add2(acc[i][jj], bb);
    }
    __syncthreads();

    load_row130(BufF, xf + rowoff, tid);
    load_wdup(WS, bst, Wxf, bxf, tid);
    __syncthreads();
    mm64p(WS, BufF, o0, tx, acc);
    __syncthreads();
    #pragma unroll
    for (int i = 0; i < 4; i++) {
        ull bb = pk2(bst[o0+i], bst[o0+i]);
        #pragma unroll
        for (int jj = 0; jj < 4; jj++)
            *reinterpret_cast<ull*>(BufF + (o0+i)*BSTRIDE + 2*tx + 32*jj) = add2(acc[i][jj], bb);
    }
    __syncthreads();

    load_wdup(WS, bst, Wx1, bx1, tid);
    __syncthreads();
    mm64p(WS, BufP, o0, tx, acc);
    #pragma unroll
    for (int i = 0; i < 4; i++) {
        ull bb = pk2(bst[o0+i], bst[o0+i]);
        #pragma unroll
        for (int jj = 0; jj < 4; jj++)
            *reinterpret_cast<ull*>(BufA + (o0+i)*BSTRIDE + 2*tx + 32*jj) = add2(acc[i][jj], bb);
    }
    __syncthreads();

    sc128p(BufA, BufF, o0, tx, WS);
    __syncthreads();

    mm64p(WS, BufP, o0, tx, acc);
    store_feat_planes(g_featFH, g_featFL, acc, n, y, o0, tx);
    __syncthreads();

    load_row130(BufF, xr + rowoff, tid);
    load_wdup(WS, bst, Wxr, bxr, tid);
    __syncthreads();
    mm64p(WS, BufF, o0, tx, acc);
    __syncthreads();
    #pragma unroll
    for (int i = 0; i < 4; i++) {
        ull bb = pk2(bst[o0+i], bst[o0+i]);
        #pragma unroll
        for (int jj = 0; jj < 4; jj++)
            *reinterpret_cast<ull*>(BufF + (o0+i)*BSTRIDE + 2*tx + 32*jj) = add2(acc[i][jj], bb);
    }
    __syncthreads();

    load_wdup(WS, bst, Wx2, bx2, tid);
    __syncthreads();
    mm64p(WS, BufP, o0, tx, acc);
    #pragma unroll
    for (int i = 0; i < 4; i++) {
        ull bb = pk2(bst[o0+i], bst[o0+i]);
        #pragma unroll
        for (int jj = 0; jj < 4; jj++)
            *reinterpret_cast<ull*>(BufA + (o0+i)*BSTRIDE + 2*tx + 32*jj) = add2(acc[i][jj], bb);
    }
    __syncthreads();

    sc128p(BufA, BufF, o0, tx, WS);
    __syncthreads();

    mm64p(WS, BufP, o0, tx, acc);
    store_feat_planes(g_featRH, g_featRL, acc, n, y, o0, tx);
}

// ---------------- conv kernel: mma.sync bf16, all staging via cp.async ----------------
// block=(y,n), 512 threads (16 warps: wm 0..3 -> M48, wn 0..3 -> N32).
// 18 stages (kh 0..2, cg 0..5). Per buffer:
//   A: 6 tiles [kw(3)][h/l(2)] of [192 o][32 k, 80B-stride]  = 92160 B
//   B: Bh,Bl [130 rows(x+1)][32 k, 80B-stride]               = 20800 B
#define ATILE   15360   // 192*80
#define ABUF    92160
#define BPLANE  10400   // 130*80
#define BUFB    112960  // ABUF + 2*BPLANE
#define CONV_SMEM (2*BUFB)   // 225920

__device__ __forceinline__ void conv_issueA(uint32_t dst_base, int s, int tid)
{
    const int kh = s/6, cg = s - (s/6)*6;
    #pragma unroll 3
    for (int q = tid; q < 4608; q += 512) {
        int t   = q / 768;             // kw*2 + hl
        int rem = q - t*768;
        int o   = rem >> 2, c16 = rem & 3;
        int kw  = t >> 1,   hl = t & 1;
        int slot = (kh*3 + kw)*6 + cg;
        const unsigned short* src = (hl ? g_Wl : g_Wh) + (size_t)slot*6144 + o*32 + c16*8;
        cp_async16(dst_base + t*ATILE + o*80 + c16*16, src, 16);
    }
}

__device__ __forceinline__ void conv_issueB(uint32_t dst_base, int s, int n, int y, int tid)
{
    const int kh = s/6, cg = s - (s/6)*6;
    const unsigned short *pH, *pL;
    if      (cg < 2) { pH = g_featFH; pL = g_featFL; }
    else if (cg < 4) { pH = g_featRH; pL = g_featRL; }
    else             { pH = g_xH;     pL = g_xL;     }
    const int coff = (cg & 1)*32;
    const int iy = y - 1 + kh;
    const bool vrow = (iy >= 0 && iy < HH);
    #pragma unroll 3
    for (int q = tid; q < 1040; q += 512) {
        int col = q >> 3, t = q & 7;
        int plane = t >> 2, c16 = t & 3;
        int gx = col - 1;
        bool ok = vrow && gx >= 0 && gx < WW;
        const unsigned short* p = plane ? pL : pH;
        const unsigned short* src = ok
            ? p + (((size_t)n*HH + iy)*WW + gx)*64 + coff + c16*8
            : p;
        cp_async16(dst_base + ABUF + plane*BPLANE + col*80 + c16*16, src, ok ? 16 : 0);
    }
}

__global__ void __launch_bounds__(512, 1)
conv_mma_kernel(const float* __restrict__ bmsa, const float* __restrict__ gamma,
                const float* __restrict__ beta, const float* __restrict__ mean,
                const float* __restrict__ var,  float* __restrict__ out)
{
    extern __shared__ char smem[];
    const uint32_t smem_base = smem_u32(smem);
    const int tid  = threadIdx.x;
    const int lane = tid & 31, wid = tid >> 5;
    const int wm = wid >> 2;           // 0..3 -> M offset 48*wm
    const int wn = wid & 3;            // 0..3 -> N offset 32*wn
    const int y = blockIdx.x, n = blockIdx.y;

    float acc[3][4][4];
    #pragma unroll
    for (int mi = 0; mi < 3; mi++)
        #pragma unroll
        for (int nb = 0; nb < 4; nb++)
            #pragma unroll
            for (int e = 0; e < 4; e++) acc[mi][nb][e] = 0.f;

    // prologue: stage 0 into buf0
    conv_issueA(smem_base, 0, tid);
    conv_issueB(smem_base, 0, n, y, tid);
    cp_commit();

    const int acol = (lane & 3) * 4;
    const int arow = wm*48 + (lane >> 2);
    const int brow0 = wn*32 + (lane >> 2);

    for (int s = 0; s < 18; s++) {
        const int b = s & 1;
        const char* buf = smem + b*BUFB;

        cp_wait0();
        __syncthreads();

        if (s < 17) {
            conv_issueA(smem_base + (b^1)*BUFB, s+1, tid);
            conv_issueB(smem_base + (b^1)*BUFB, s+1, n, y, tid);
            cp_commit();
        }

        const char* Bh = buf + ABUF;
        const char* Bl = buf + ABUF + BPLANE;

        #pragma unroll
        for (int kw = 0; kw < 3; kw++) {
            const char* Ah = buf + (kw*2 + 0)*ATILE;
            const char* Al = buf + (kw*2 + 1)*ATILE;
            #pragma unroll
            for (int ks = 0; ks < 2; ks++) {
                const int koff = ks*32 + acol;
                uint32_t aF[3][4];
                uint32_t bH[4][2], bL[4][2];
                // B frags (kept in regs across product passes)
                #pragma unroll
                for (int nb = 0; nb < 4; nb++) {
                    const char* q = Bh + (brow0 + nb*8 + kw)*80 + koff;
                    bH[nb][0] = *reinterpret_cast<const uint32_t*>(q);
                    bH[nb][1] = *reinterpret_cast<const uint32_t*>(q + 16);
                    const char* r = Bl + (brow0 + nb*8 + kw)*80 + koff;
                    bL[nb][0] = *reinterpret_cast<const uint32_t*>(r);
                    bL[nb][1] = *reinterpret_cast<const uint32_t*>(r + 16);
                }
                // Ah frags: Ah*Bh + Ah*Bl
                #pragma unroll
                for (int mi = 0; mi < 3; mi++) {
                    const char* p = Ah + (arow + mi*16)*80 + koff;
                    aF[mi][0] = *reinterpret_cast<const uint32_t*>(p);
                    aF[mi][1] = *reinterpret_cast<const uint32_t*>(p + 8*80);
                    aF[mi][2] = *reinterpret_cast<const uint32_t*>(p + 16);
                    aF[mi][3] = *reinterpret_cast<const uint32_t*>(p + 8*80 + 16);
                }
                #pragma unroll
                for (int nb = 0; nb < 4; nb++)
                    #pragma unroll
                    for (int mi = 0; mi < 3; mi++) {
                        mma16816(acc[mi][nb], aF[mi], bH[nb][0], bH[nb][1]);
                        mma16816(acc[mi][nb], aF[mi], bL[nb][0], bL[nb][1]);
                    }
                // Al frags: Al*Bh
                #pragma unroll
                for (int mi = 0; mi < 3; mi++) {
                    const char* p = Al + (arow + mi*16)*80 + koff;
                    aF[mi][0] = *reinterpret_cast<const uint32_t*>(p);
                    aF[mi][1] = *reinterpret_cast<const uint32_t*>(p + 8*80);
                    aF[mi][2] = *reinterpret_cast<const uint32_t*>(p + 16);
                    aF[mi][3] = *reinterpret_cast<const uint32_t*>(p + 8*80 + 16);
                }
                #pragma unroll
                for (int nb = 0; nb < 4; nb++)
                    #pragma unroll
                    for (int mi = 0; mi < 3; mi++)
                        mma16816(acc[mi][nb], aF[mi], bH[nb][0], bH[nb][1]);
            }
        }
    }

    // ---- epilogue: bias + BN + ReLU, float2 stores ----
    #pragma unroll
    for (int mi = 0; mi < 3; mi++) {
        #pragma unroll
        for (int h = 0; h < 2; h++) {
            const int o = wm*48 + mi*16 + (lane >> 2) + h*8;
            const float sc = gamma[o] * rsqrtf(var[o] + 1e-4f);
            const float t0 = (bmsa[o] - mean[o]) * sc + beta[o];
            float* orow = out + (((size_t)n*192 + o)*HH + y)*WW;
            #pragma unroll
            for (int nb = 0; nb < 4; nb++) {
                const int x0 = wn*32 + nb*8 + (lane & 3)*2;
                float v0 = fmaxf(fmaf(acc[mi][nb][h*2+0], sc, t0), 0.f);
                float v1 = fmaxf(fmaf(acc[mi][nb][h*2+1], sc, t0), 0.f);
                *reinterpret_cast<ull*>(orow + x0) = pk2(v0, v1);
            }
        }
    }
}

// ---------------- launch ----------------
extern "C" void kernel_launch(void* const* d_in, const int* in_sizes, int n_in,
                              void* d_out, int out_size)
{
    const float* x    = (const float*)d_in[0];
    const float* xf   = (const float*)d_in[1];
    const float* xr   = (const float*)d_in[2];
    const float* Wx   = (const float*)d_in[3];
    const float* bx   = (const float*)d_in[4];
    const float* Wx1  = (const float*)d_in[5];
    const float* bx1  = (const float*)d_in[6];
    const float* Wx2  = (const float*)d_in[7];
    const float* bx2  = (const float*)d_in[8];
    const float* Wxf  = (const float*)d_in[9];
    const float* bxf  = (const float*)d_in[10];
    const float* Wxr  = (const float*)d_in[11];
    const float* bxr  = (const float*)d_in[12];
    const float* Wmsa = (const float*)d_in[13];
    const float* bmsa = (const float*)d_in[14];
    const float* gam  = (const float*)d_in[15];
    const float* bet  = (const float*)d_in[16];
    const float* mu   = (const float*)d_in[17];
    const float* var  = (const float*)d_in[18];
    float* out = (float*)d_out;

    cudaFuncSetAttribute(attn_kernel, cudaFuncAttributeMaxDynamicSharedMemorySize, SMEM1_BYTES);
    cudaFuncSetAttribute(conv_mma_kernel, cudaFuncAttributeMaxDynamicSharedMemorySize, CONV_SMEM);

    wprep_kernel<<<54, 256>>>(Wmsa);
    dim3 gx2(HH, BB);
    xprep_kernel<<<gx2, 256>>>(x);

    dim3 g1(HH, BB);
    attn_kernel<<<g1, 256, SMEM1_BYTES>>>(x, xf, xr, Wx, bx, Wx1, bx1, Wx2, bx2,
                                          Wxf, bxf, Wxr, bxr);

    dim3 g2(HH, BB);
    conv_mma_kernel<<<g2, 512, CONV_SMEM>>>(bmsa, gam, bet, mu, var, out);
}